// round 6
// baseline (speedup 1.0000x reference)
#include <cuda_runtime.h>

#define THREADS 256
#define TB 16
// smem: wp [m][n][4] 64KB + wm 64KB + 2 x-buffers of 32KB = 192KB
#define SMEM_BYTES 196608

typedef unsigned long long ull;

__device__ __forceinline__ ull pk2(float lo, float hi) {
    ull r;
    asm("mov.b64 %0, {%1, %2};" : "=l"(r) : "f"(lo), "f"(hi));
    return r;
}
__device__ __forceinline__ void unpk(ull v, float& lo, float& hi) {
    asm("mov.b64 {%0, %1}, %2;" : "=f"(lo), "=f"(hi) : "l"(v));
}
__device__ __forceinline__ ull ffma2(ull a, ull b, ull c) {
    ull d;
    asm("fma.rn.f32x2 %0, %1, %2, %3;" : "=l"(d) : "l"(a), "l"(b), "l"(c));
    return d;
}

// ---------------------------------------------------------------------------
// stage one tile (TB=16 batches = 32KB) into smem, TRANSPOSED to [m][b][8]
// m-stride = TB*32B = 512B  ->  addr = (m<<9) + (b<<5) + (h<<4), then
// swizzle  addr ^= (m&7)<<4  (flips h by m&1 and b's low 2 bits by (m>>1)&3).
// ---------------------------------------------------------------------------
__device__ __forceinline__ void stage_tile(const float* __restrict__ x,
                                           char* dstbase, int tile, int tid) {
    const float4* src = reinterpret_cast<const float4*>(x) + (size_t)tile * 2048;
#pragma unroll
    for (int r = 0; r < 8; r++) {
        int i = tid + r * 256;          // float4 index within tile
        int b = i >> 7;                 // 0..15
        int mh = i & 127;
        int m = mh >> 1;                // 0..63
        int h = mh & 1;                 // 16B half
        unsigned int db = ((unsigned)m << 9) + ((unsigned)b << 5) + ((unsigned)h << 4);
        db ^= (unsigned)(m & 7) << 4;
        unsigned int ds = (unsigned int)__cvta_generic_to_shared(dstbase + db);
        asm volatile("cp.async.cg.shared.global [%0], [%1], 16;\n"
                     :: "r"(ds), "l"(src + i));
    }
    asm volatile("cp.async.commit_group;\n");
}

__global__ __launch_bounds__(THREADS, 1)
void clifford_gate_kernel(const float* __restrict__ x,
                          const float* __restrict__ wp,
                          const float* __restrict__ bpr,
                          const float* __restrict__ wm,
                          const float* __restrict__ bmr,
                          float* __restrict__ out,
                          int ntiles) {
    extern __shared__ float smf[];
    float4* wsp = reinterpret_cast<float4*>(smf);          // 4096 float4, [m*64+n]
    float4* wsm = wsp + 4096;                               // 4096 float4
    char*   xb  = reinterpret_cast<char*>(smf + 32768);     // 2 x 32KB, [m][b][8] swz

    const int tid  = threadIdx.x;
    const int lane = tid & 31;
    const int warp = tid >> 5;
    const int n = (warp << 3) | (lane & 7);   // 8 warps x 8 n = 64 n
    const int k = lane >> 3;                  // bb subgroup 0..3; bb = k + 4j

    // per-thread swizzled subgroup offsets: kb[q] = 32*(k ^ q)
    int kb[4];
#pragma unroll
    for (int q = 0; q < 4; q++) kb[q] = 32 * (k ^ q);

    // ---- stage weights once: gmem [n][m][4] -> smem [m][n][4] ----
    {
        const float4* gp = reinterpret_cast<const float4*>(wp);
        const float4* gm = reinterpret_cast<const float4*>(wm);
        for (int idx = tid; idx < 4096; idx += THREADS) {
            int nn = idx & 63, mm = idx >> 6;
            wsp[mm * 64 + nn] = gp[nn * 64 + mm];
            wsm[mm * 64 + nn] = gm[nn * 64 + mm];
        }
    }
    const float biasp = bpr[n];
    const float biasm = bmr[n];

    int t = blockIdx.x;
    const int stride = gridDim.x;
    if (t < ntiles) stage_tile(x, xb, t, tid);
    asm volatile("cp.async.wait_group 0;\n");
    __syncthreads();

    int cur = 0;
    const float s2 = 0.70710678118654752440f;

    for (; t < ntiles; t += stride) {
        int tn = t + stride;
        if (tn < ntiles) stage_tile(x, xb + (cur ^ 1) * 32768, tn, tid);

        // ---------------- mainloop: packed f32x2 GEMM ----------------
        // Per-element reduction: single accumulator, m ascending, fused fma —
        // DO NOT change (bit-exact vs reference; gate/q are singular).
        ull aP[4][4], aM[4][4];
#pragma unroll
        for (int i = 0; i < 4; i++)
#pragma unroll
            for (int j = 0; j < 4; j++) { aP[i][j] = 0ull; aM[i][j] = 0ull; }

        const char* xc = xb + cur * 32768;

#pragma unroll 1
        for (int mo = 0; mo < 64; mo += 8) {
#pragma unroll
            for (int mi = 0; mi < 8; mi++) {
                const int m = mo + mi;
                float4 wpv = wsp[(m << 6) + n];
                float4 wmv = wsm[(m << 6) + n];
                // packs: A=(w0,w1), D=(w2,w3) are the raw float4 halves
                ull wpA, wpD, wmA, wmD;
                {
                    const ulonglong2* u = reinterpret_cast<const ulonglong2*>(&wpv);
                    wpA = u->x; wpD = u->y;
                    const ulonglong2* v = reinterpret_cast<const ulonglong2*>(&wmv);
                    wmA = v->x; wmD = v->y;
                }
                ull wpB = pk2(wpv.y, wpv.y), wpC = pk2(wpv.z, wpv.z);
                ull wmB = pk2(wmv.y, wmv.y), wmC = pk2(wmv.z, wmv.z);

                const int q   = (mi >> 1) & 3;   // compile-time per mi
                const int e   = (mi & 1) << 4;   // swizzle bit4 of this m
                const char* pb = xc + kb[q] + (m << 9);
#pragma unroll
                for (int j = 0; j < 4; j++) {
                    // chunk h0 = blades 0-3, h1 = blades 4-7 (swizzle may swap
                    // their 16B slots; e compensates)
                    const char* pj = pb + (j << 7);
                    ulonglong2 c0 = *reinterpret_cast<const ulonglong2*>(pj + e);
                    ulonglong2 c1 = *reinterpret_cast<const ulonglong2*>(pj + (16 - e));
                    aP[j][0] = ffma2(c0.x, wpA, aP[j][0]);
                    aP[j][1] = ffma2(c0.y, wpB, aP[j][1]);
                    aP[j][2] = ffma2(c1.x, wpC, aP[j][2]);
                    aP[j][3] = ffma2(c1.y, wpD, aP[j][3]);
                    aM[j][0] = ffma2(c0.x, wmA, aM[j][0]);
                    aM[j][1] = ffma2(c0.y, wmB, aM[j][1]);
                    aM[j][2] = ffma2(c1.x, wmC, aM[j][2]);
                    aM[j][3] = ffma2(c1.y, wmD, aM[j][3]);
                }
            }
        }

        // ---------------- epilogue ----------------
#pragma unroll
        for (int j = 0; j < 4; j++) {
            float p0, p1, p2, p3, p4, p5, p6, p7;
            float m0, m1, m2, m3, m4, m5, m6, m7;
            unpk(aP[j][0], p0, p1); unpk(aP[j][1], p2, p3);
            unpk(aP[j][2], p4, p5); unpk(aP[j][3], p6, p7);
            unpk(aM[j][0], m0, m1); unpk(aM[j][1], m2, m3);
            unpk(aM[j][2], m4, m5); unpk(aM[j][3], m6, m7);
            p0 = __fadd_rn(p0, biasp);
            m0 = __fadd_rn(m0, biasm);

            // gate: individually rounded multiplies + sequential adds i=0..7.
            // NO FMA here (bit-exactness near b==0 is required).
            float bgv;
            bgv = __fmul_rn(p0, m0);
            bgv = __fadd_rn(bgv, __fmul_rn(p1, m1));
            bgv = __fadd_rn(bgv, __fmul_rn(p2, m2));
            bgv = __fadd_rn(bgv, __fmul_rn(p3, m3));
            bgv = __fadd_rn(bgv, __fmul_rn(p4, m4));
            bgv = __fadd_rn(bgv, __fmul_rn(p5, m5));
            bgv = __fadd_rn(bgv, __fmul_rn(p6, m6));
            bgv = __fadd_rn(bgv, __fmul_rn(p7, m7));

            // q: same rounding discipline (singular near q==0).
            float qv;
            qv = __fmul_rn(m0, m0);
            qv = __fadd_rn(qv, __fmul_rn(m1, m1));
            qv = __fadd_rn(qv, __fmul_rn(m2, m2));
            qv = __fadd_rn(qv, __fmul_rn(m3, m3));
            qv = __fadd_rn(qv, -__fmul_rn(m4, m4));
            qv = __fadd_rn(qv, -__fmul_rn(m5, m5));
            qv = __fadd_rn(qv, -__fmul_rn(m6, m6));
            qv = __fadd_rn(qv, -__fmul_rn(m7, m7));

            float qs  = __fadd_rn(__fmul_rn(qv, qv), 1e-16f);
            float nrm = __fsqrt_rn(__fsqrt_rn(qs));
            float inv = __frcp_rn(nrm);

            float n0 = m0 * inv, n1 = m1 * inv, n2 = m2 * inv, n3 = m3 * inv;
            float n4 = m4 * inv, n5 = m5 * inv, n6 = m6 * inv, n7 = m7 * inv;

            // Cl(3,0) geometric product r = p * n (well-conditioned; fma ok)
            float r0 = p0*n0 + p1*n1 + p2*n2 + p3*n3 - p4*n4 - p5*n5 - p6*n6 - p7*n7;
            float r1 = p0*n1 + p1*n0 - p2*n4 + p4*n2 - p3*n5 + p5*n3 - p6*n7 - p7*n6;
            float r2 = p0*n2 + p2*n0 + p1*n4 - p4*n1 - p3*n6 + p6*n3 + p5*n7 + p7*n5;
            float r3 = p0*n3 + p3*n0 + p1*n5 - p5*n1 + p2*n6 - p6*n2 - p4*n7 - p7*n4;
            float r4 = p0*n4 + p4*n0 + p1*n2 - p2*n1 + p3*n7 + p7*n3 - p5*n6 + p6*n5;
            float r5 = p0*n5 + p5*n0 + p1*n3 - p3*n1 - p2*n7 - p7*n2 + p4*n6 - p6*n4;
            float r6 = p0*n6 + p6*n0 + p1*n7 + p7*n1 + p2*n3 - p3*n2 - p4*n5 + p5*n4;
            float r7 = p0*n7 + p7*n0 + p1*n6 + p6*n1 - p2*n5 - p5*n2 + p3*n4 + p4*n3;

            bool sel = bgv > 0.0f;
            float4 o0, o1;
            o0.x = (sel ? p0 : r0) * s2;
            o0.y = (sel ? p1 : r1) * s2;
            o0.z = (sel ? p2 : r2) * s2;
            o0.w = (sel ? p3 : r3) * s2;
            o1.x = (sel ? p4 : r4) * s2;
            o1.y = (sel ? p5 : r5) * s2;
            o1.z = (sel ? p6 : r6) * s2;
            o1.w = (sel ? p7 : r7) * s2;

            size_t brow = (size_t)t * TB + (size_t)(k + 4 * j);
            float4* op = reinterpret_cast<float4*>(out + ((brow << 6) + n) * 8);
            op[0] = o0;
            op[1] = o1;
        }

        asm volatile("cp.async.wait_group 0;\n");
        __syncthreads();
        cur ^= 1;
    }
}

extern "C" void kernel_launch(void* const* d_in, const int* in_sizes, int n_in,
                              void* d_out, int out_size) {
    const float* x   = (const float*)d_in[0];
    const float* wp  = (const float*)d_in[1];
    const float* bpr = (const float*)d_in[2];
    const float* wm  = (const float*)d_in[3];
    const float* bmr = (const float*)d_in[4];
    float* out = (float*)d_out;

    int B = in_sizes[0] / 512;      // x is (B, 64, 8)
    int ntiles = B / TB;

    cudaFuncSetAttribute(clifford_gate_kernel,
                         cudaFuncAttributeMaxDynamicSharedMemorySize, SMEM_BYTES);

    int dev = 0, sms = 148;
    cudaGetDevice(&dev);
    cudaDeviceGetAttribute(&sms, cudaDevAttrMultiProcessorCount, dev);
    int grid = sms < ntiles ? sms : ntiles;
    if (grid < 1) grid = 1;

    clifford_gate_kernel<<<grid, THREADS, SMEM_BYTES>>>(
        x, wp, bpr, wm, bmr, out, ntiles);
}